// round 17
// baseline (speedup 1.0000x reference)
#include <cuda_runtime.h>
#include <cstdint>

// Persistent device state.
// g_spike_count: exact spike count. Starts 0; spike_count_kernel adds to it;
//   the LAST block of delta_kernel resets it to 0, restoring the invariant
//   for the next graph replay. Kernel boundaries provide all the ordering.
// g_done: ticket counter for delta_kernel's last-block election; atomicInc
//   with limit gridDim.x-1 self-wraps to 0 each launch.
__device__ unsigned long long g_spike_count = 0ull;
__device__ unsigned int       g_done        = 0u;

// Pass 1: out_spikes = (spikes >= 0.5f) and exact spike count.
// 2-way unrolled float4 grid-stride (MLP=2). One atomicAdd per block, no
// fences, no tickets — the kernel boundary orders everything for pass 2.
__global__ void __launch_bounds__(256) spike_count_kernel(
    const float4* __restrict__ spikes4,
    float4* __restrict__ out_spikes4,
    int n4)
{
    unsigned int local = 0u;
    const int tid    = blockIdx.x * blockDim.x + threadIdx.x;
    const int stride = gridDim.x * blockDim.x;

    int i = tid;
    // Main 2-way unrolled loop: two independent loads in flight.
    for (; i + stride < n4; i += 2 * stride) {
        float4 v0 = __ldg(&spikes4[i]);
        float4 v1 = __ldg(&spikes4[i + stride]);

        float4 o0, o1;
        o0.x = (v0.x >= 0.5f) ? 1.0f : 0.0f;
        o0.y = (v0.y >= 0.5f) ? 1.0f : 0.0f;
        o0.z = (v0.z >= 0.5f) ? 1.0f : 0.0f;
        o0.w = (v0.w >= 0.5f) ? 1.0f : 0.0f;
        o1.x = (v1.x >= 0.5f) ? 1.0f : 0.0f;
        o1.y = (v1.y >= 0.5f) ? 1.0f : 0.0f;
        o1.z = (v1.z >= 0.5f) ? 1.0f : 0.0f;
        o1.w = (v1.w >= 0.5f) ? 1.0f : 0.0f;

        local += (unsigned)(v0.x >= 0.5f) + (unsigned)(v0.y >= 0.5f)
               + (unsigned)(v0.z >= 0.5f) + (unsigned)(v0.w >= 0.5f)
               + (unsigned)(v1.x >= 0.5f) + (unsigned)(v1.y >= 0.5f)
               + (unsigned)(v1.z >= 0.5f) + (unsigned)(v1.w >= 0.5f);

        out_spikes4[i]          = o0;
        out_spikes4[i + stride] = o1;
    }
    // Remainder (at most one element per thread).
    if (i < n4) {
        float4 v = __ldg(&spikes4[i]);
        float4 o;
        o.x = (v.x >= 0.5f) ? 1.0f : 0.0f;
        o.y = (v.y >= 0.5f) ? 1.0f : 0.0f;
        o.z = (v.z >= 0.5f) ? 1.0f : 0.0f;
        o.w = (v.w >= 0.5f) ? 1.0f : 0.0f;
        local += (unsigned)(v.x >= 0.5f) + (unsigned)(v.y >= 0.5f)
               + (unsigned)(v.z >= 0.5f) + (unsigned)(v.w >= 0.5f);
        out_spikes4[i] = o;
    }

    // Warp reduce
    #pragma unroll
    for (int off = 16; off > 0; off >>= 1)
        local += __shfl_down_sync(0xFFFFFFFFu, local, off);

    // Block reduce via smem
    __shared__ unsigned int warp_sums[8];
    const int lane = threadIdx.x & 31;
    const int wid  = threadIdx.x >> 5;
    if (lane == 0) warp_sums[wid] = local;
    __syncthreads();
    if (wid == 0) {
        unsigned int s = (lane < (blockDim.x >> 5)) ? warp_sums[lane] : 0u;
        #pragma unroll
        for (int off = 4; off > 0; off >>= 1)
            s += __shfl_down_sync(0xFFFFFFFFu, s, off);
        if (lane == 0)
            atomicAdd(&g_spike_count, (unsigned long long)s);
    }
}

// Pass 2: delta = S - P, S = g_spike_count / N (count is final: kernel
// boundary ordered it). Last-finishing block resets the counter for replay.
__global__ void __launch_bounds__(256) delta_kernel(
    const float4* __restrict__ P4,
    float4* __restrict__ delta4,
    int n4,
    double inv_n)
{
    // Uniform load of the completed count; exact integer -> double -> float.
    const float S = (float)((double)g_spike_count * inv_n);

    const int tid    = blockIdx.x * blockDim.x + threadIdx.x;
    const int stride = gridDim.x * blockDim.x;

    int i = tid;
    for (; i + stride < n4; i += 2 * stride) {
        float4 p0 = __ldg(&P4[i]);
        float4 p1 = __ldg(&P4[i + stride]);
        float4 d0, d1;
        d0.x = S - p0.x; d0.y = S - p0.y; d0.z = S - p0.z; d0.w = S - p0.w;
        d1.x = S - p1.x; d1.y = S - p1.y; d1.z = S - p1.z; d1.w = S - p1.w;
        delta4[i]          = d0;
        delta4[i + stride] = d1;
    }
    if (i < n4) {
        float4 p = __ldg(&P4[i]);
        float4 d;
        d.x = S - p.x; d.y = S - p.y; d.z = S - p.z; d.w = S - p.w;
        delta4[i] = d;
    }

    // Last block to finish resets the spike counter for the next replay.
    // Safe: every block read g_spike_count at its start, and the last ticket
    // fires only after all blocks completed. atomicInc self-wraps g_done.
    if (threadIdx.x == 0) {
        unsigned int ticket = atomicInc(&g_done, gridDim.x - 1u);
        if (ticket == gridDim.x - 1u)
            g_spike_count = 0ull;
    }
}

extern "C" void kernel_launch(void* const* d_in, const int* in_sizes, int n_in,
                              void* d_out, int out_size)
{
    const float* spikes = (const float*)d_in[0];
    const float* P      = (const float*)d_in[1];
    float* out          = (float*)d_out;

    const int n  = in_sizes[0];        // 33554432, divisible by 4
    const int n4 = n >> 2;

    float* delta_out  = out;           // output[0]: delta [n]
    float* spikes_out = out + n;       // output[1]: out_spikes [n]

    const int threads = 256;
    // One full wave on GB300: 152 SMs x 8 CTAs of 256 threads.
    int blocks = 152 * 8;              // 1216
    int needed = (n4 + threads - 1) / threads;
    if (blocks > needed) blocks = needed;

    spike_count_kernel<<<blocks, threads>>>(
        (const float4*)spikes, (float4*)spikes_out, n4);
    delta_kernel<<<blocks, threads>>>(
        (const float4*)P, (float4*)delta_out, n4, 1.0 / (double)n);
}